// round 16
// baseline (speedup 1.0000x reference)
#include <cuda_runtime.h>
#include <cuda_fp16.h>

// Problem constants
#define N_   8
#define C_   64
#define H_   256
#define W_   256
#define HO_  256
#define WO_  256
#define HW_  (H_ * W_)

// NHWC fp16 scratch for all images (67 MB). No allocation.
__device__ __half g_xt[(size_t)N_ * HW_ * C_];

static __device__ __forceinline__ unsigned int h2_as_u(__half2 h) {
    return *reinterpret_cast<unsigned int*>(&h);
}
static __device__ __forceinline__ __half2 u_as_h2(unsigned int u) {
    return *reinterpret_cast<__half2*>(&u);
}

// Shared memory union: T and S staging never live in the same block.
union SmemU {
    unsigned int smw[64 * 64];              // T: [ch][pixpair] 16 KB
    struct {
        int4         soff[64];              // S: corner byte offsets
        uint4        swq[64];               // S: weights as half2
        unsigned int smq[64 * 33];          // S: half2 result staging
    } s;
};

// -------------------------------------------------------------------------
// T body (R6, proven): 128 px x 64 ch of image n, NCHW fp32 -> NHWC fp16.
// -------------------------------------------------------------------------
static __device__ __forceinline__ void t_chunk(const float* __restrict__ x,
                                               int n, int tb, SmemU* u, int tid) {
    const int s0  = tb * 128;
    const float* xin = x + (size_t)n * (C_ * HW_);
    const int lane = tid & 31;
    const int cb   = tid >> 5;

    #pragma unroll
    for (int i = 0; i < 8; i++) {
        const int c = i * 8 + cb;
        const float4 v = __ldcs((const float4*)(xin + (size_t)c * HW_ + s0) + lane);
        const unsigned int u0 = h2_as_u(__floats2half2_rn(v.x, v.y));
        const unsigned int u1 = h2_as_u(__floats2half2_rn(v.z, v.w));
        const int w0 = c * 64 + lane * 2;
        const int ws = w0 ^ (((c >> 3) & 7) << 2);
        *(uint2*)&u->smw[ws] = make_uint2(u0, u1);
    }
    __syncthreads();

    uint4* ob = (uint4*)(g_xt + ((size_t)n * HW_ + s0) * C_);
    #pragma unroll
    for (int j = 0; j < 2; j++) {
        const int uu = tid + 256 * j;
        const int p2 = (uu >> 3) * 2;
        const int c8 = uu & 7;
        const int c0 = c8 * 8;
        const int sw = c8 << 2;

        unsigned int w8[8];
        #pragma unroll
        for (int jj = 0; jj < 8; jj++) {
            const int w = (c0 + jj) * 64 + (p2 >> 1);
            w8[jj] = u->smw[w ^ sw];
        }
        uint4 lo, hi;
        lo.x = __byte_perm(w8[0], w8[1], 0x5410);
        lo.y = __byte_perm(w8[2], w8[3], 0x5410);
        lo.z = __byte_perm(w8[4], w8[5], 0x5410);
        lo.w = __byte_perm(w8[6], w8[7], 0x5410);
        hi.x = __byte_perm(w8[0], w8[1], 0x7632);
        hi.y = __byte_perm(w8[2], w8[3], 0x7632);
        hi.z = __byte_perm(w8[4], w8[5], 0x7632);
        hi.w = __byte_perm(w8[6], w8[7], 0x7632);

        ob[p2 * 8 + c8]       = lo;
        ob[(p2 + 1) * 8 + c8] = hi;
    }
}

// -------------------------------------------------------------------------
// S body (R11, proven): 64 output pixels of one (n, ho) row.
// -------------------------------------------------------------------------
static __device__ __forceinline__ void s_chunk(const float* __restrict__ grid,
                                               float* __restrict__ out,
                                               int n, int sbi, SmemU* u, int tid) {
    const int wo_base = (sbi & 3) * 64;
    const int ho      = sbi >> 2;
    const int warp = tid >> 5;
    const int lane = tid & 31;

    // Phase A: warp-local coordinate setup (pixels warp*8 .. warp*8+7).
    if (lane < 8) {
        const int p = warp * 8 + lane;
        const float2* gp =
            (const float2*)(grid + (((size_t)n * HO_ + ho) * WO_ + wo_base) * 2);
        const float2 g = __ldcs(&gp[p]);

        const float ix = (g.x + 1.0f) * 0.5f * (float)(W_ - 1);
        const float iy = (g.y + 1.0f) * 0.5f * (float)(H_ - 1);

        const float x0f = floorf(ix);
        const float y0f = floorf(iy);
        const float wx1 = ix - x0f;
        const float wy1 = iy - y0f;
        const float wx0 = 1.0f - wx1;
        const float wy0 = 1.0f - wy1;

        const int xi = (int)x0f;
        const int yi = (int)y0f;
        const int x0 = min(max(xi,     0), W_ - 1);
        const int x1 = min(max(xi + 1, 0), W_ - 1);
        const int y0 = min(max(yi,     0), H_ - 1);
        const int y1 = min(max(yi + 1, 0), H_ - 1);

        int4 o;                                   // byte offsets (row = 128B)
        o.x = (y0 * W_ + x0) * (C_ * 2);
        o.y = (y0 * W_ + x1) * (C_ * 2);
        o.z = (y1 * W_ + x0) * (C_ * 2);
        o.w = (y1 * W_ + x1) * (C_ * 2);
        u->s.soff[p] = o;

        uint4 wq;
        wq.x = h2_as_u(__float2half2_rn(wy0 * wx0));
        wq.y = h2_as_u(__float2half2_rn(wy0 * wx1));
        wq.z = h2_as_u(__float2half2_rn(wy1 * wx0));
        wq.w = h2_as_u(__float2half2_rn(wy1 * wx1));
        u->s.swq[p] = wq;
    }
    __syncwarp();

    const char* xb = (const char*)(g_xt + (size_t)n * ((size_t)HW_ * C_));
    const int psel = lane >> 3;
    const int sub  = lane & 7;
    const int sb   = sub * 16;

    #pragma unroll
    for (int g = 0; g < 2; g++) {
        const int p = warp * 8 + g * 4 + psel;
        const int4  o  = u->s.soff[p];
        const uint4 wq = u->s.swq[p];

        const uint4 v00 = *(const uint4*)(xb + o.x + sb);
        const uint4 v01 = *(const uint4*)(xb + o.y + sb);
        const uint4 v10 = *(const uint4*)(xb + o.z + sb);
        const uint4 v11 = *(const uint4*)(xb + o.w + sb);

        const __half2 w00 = u_as_h2(wq.x);
        const __half2 w01 = u_as_h2(wq.y);
        const __half2 w10 = u_as_h2(wq.z);
        const __half2 w11 = u_as_h2(wq.w);

        unsigned int r[4];
        {
            __half2 a;
            a = __hmul2(u_as_h2(v00.x), w00);
            a = __hfma2(u_as_h2(v01.x), w01, a);
            a = __hfma2(u_as_h2(v10.x), w10, a);
            a = __hfma2(u_as_h2(v11.x), w11, a);
            r[0] = h2_as_u(a);
            a = __hmul2(u_as_h2(v00.y), w00);
            a = __hfma2(u_as_h2(v01.y), w01, a);
            a = __hfma2(u_as_h2(v10.y), w10, a);
            a = __hfma2(u_as_h2(v11.y), w11, a);
            r[1] = h2_as_u(a);
            a = __hmul2(u_as_h2(v00.z), w00);
            a = __hfma2(u_as_h2(v01.z), w01, a);
            a = __hfma2(u_as_h2(v10.z), w10, a);
            a = __hfma2(u_as_h2(v11.z), w11, a);
            r[2] = h2_as_u(a);
            a = __hmul2(u_as_h2(v00.w), w00);
            a = __hfma2(u_as_h2(v01.w), w01, a);
            a = __hfma2(u_as_h2(v10.w), w10, a);
            a = __hfma2(u_as_h2(v11.w), w11, a);
            r[3] = h2_as_u(a);
        }
        #pragma unroll
        for (int k = 0; k < 4; k++)
            u->s.smq[p * 33 + sub * 4 + k] = r[k];
    }
    __syncthreads();

    float* obase = out + (size_t)n * (C_ * HO_ * WO_) + (size_t)ho * WO_ + wo_base;
    #pragma unroll
    for (int it = 0; it < 4; it++) {
        const int uu = tid + 256 * it;
        const int c  = uu >> 4;
        const int q  = uu & 15;
        const int cp = c >> 1;
        const int hi = c & 1;

        float4 v;
        {
            const __half2 h0 = u_as_h2(u->s.smq[(q * 4 + 0) * 33 + cp]);
            const __half2 h1 = u_as_h2(u->s.smq[(q * 4 + 1) * 33 + cp]);
            const __half2 h2 = u_as_h2(u->s.smq[(q * 4 + 2) * 33 + cp]);
            const __half2 h3 = u_as_h2(u->s.smq[(q * 4 + 3) * 33 + cp]);
            v.x = hi ? __high2float(h0) : __low2float(h0);
            v.y = hi ? __high2float(h1) : __low2float(h1);
            v.z = hi ? __high2float(h2) : __low2float(h2);
            v.w = hi ? __high2float(h3) : __low2float(h3);
        }
        __stcs((float4*)(obase + (size_t)c * (HO_ * WO_) + q * 4), v);
    }
}

// -------------------------------------------------------------------------
// Pure transpose launch: images [n0, n0 + gridDim.y).
// -------------------------------------------------------------------------
__global__ __launch_bounds__(256, 5) void t_kernel(const float* __restrict__ x,
                                                   int n0) {
    __shared__ SmemU u;
    t_chunk(x, n0 + blockIdx.y, blockIdx.x, &u, threadIdx.x);
}

// -------------------------------------------------------------------------
// Mixed launch: 3072 blocks. bid%3==0 -> T images [nt0, nt0+2),
// else -> S images [ns0, ns0+2). S deps completed at the previous launch
// boundary — no intra-kernel sync needed.
// -------------------------------------------------------------------------
__global__ __launch_bounds__(256, 5) void mixed_kernel(
    const float* __restrict__ x, const float* __restrict__ grid,
    float* __restrict__ out, int nt0, int ns0) {
    __shared__ SmemU u;
    const int bid = blockIdx.x;
    const int tid = threadIdx.x;
    const int m   = bid % 3;
    const int d   = bid / 3;              // 0..1023

    if (m == 0) {                         // 1024 T blocks: 2 images
        const int img = nt0 + (d >> 9);
        t_chunk(x, img, d & 511, &u, tid);
    } else {                              // 2048 S blocks: 2 images
        const int sidx = d * 2 + (m - 1); // 0..2047
        const int img  = ns0 + (sidx >> 10);
        s_chunk(grid, out, img, sidx & 1023, &u, tid);
    }
}

// -------------------------------------------------------------------------
// Pure sample launch: images [n0, n0 + gridDim.y).
// -------------------------------------------------------------------------
__global__ __launch_bounds__(256, 5) void s_kernel(
    const float* __restrict__ grid, float* __restrict__ out, int n0) {
    __shared__ SmemU u;
    s_chunk(grid, out, n0 + blockIdx.y, blockIdx.x, &u, threadIdx.x);
}

extern "C" void kernel_launch(void* const* d_in, const int* in_sizes, int n_in,
                              void* d_out, int out_size) {
    const float* x    = (const float*)d_in[0];   // [N, C, H, W]
    const float* grid = (const float*)d_in[1];   // [N, HO, WO, 2]
    float* out        = (float*)d_out;           // [N, C, HO, WO]
    (void)in_sizes; (void)n_in; (void)out_size;

    // 2-image software pipeline over launch boundaries:
    // T(01) | T(23)+S(01) | T(45)+S(23) | T(67)+S(45) | S(67)
    t_kernel<<<dim3(512, 2), 256>>>(x, 0);
    mixed_kernel<<<3072, 256>>>(x, grid, out, 2, 0);
    mixed_kernel<<<3072, 256>>>(x, grid, out, 4, 2);
    mixed_kernel<<<3072, 256>>>(x, grid, out, 6, 4);
    s_kernel<<<dim3(1024, 2), 256>>>(grid, out, 6);
}

// round 17
// speedup vs baseline: 1.0616x; 1.0616x over previous
#include <cuda_runtime.h>
#include <cuda_fp16.h>

// Problem constants
#define N_   8
#define C_   64
#define H_   256
#define W_   256
#define HO_  256
#define WO_  256
#define HW_  (H_ * W_)

// NHWC fp16 scratch for all images (67 MB). No allocation.
__device__ __half g_xt[(size_t)N_ * HW_ * C_];

static __device__ __forceinline__ unsigned int h2_as_u(__half2 h) {
    return *reinterpret_cast<unsigned int*>(&h);
}
static __device__ __forceinline__ __half2 u_as_h2(unsigned int u) {
    return *reinterpret_cast<__half2*>(&u);
}

// Shared memory union: T and S staging never live in the same block.
union SmemU {
    unsigned int smw[64 * 64];              // T: [ch][pixpair] 16 KB
    struct {
        int4         soff[64];              // S: corner byte offsets
        uint4        swq[64];               // S: weights as half2
        unsigned int smq[64 * 33];          // S: half2 result staging
    } s;
};

// -------------------------------------------------------------------------
// T body: 128 px x 64 ch of image n, NCHW fp32 -> NHWC fp16.
// R6 body + 4-deep load batching (all 4 LDG.128 issued before converts).
// -------------------------------------------------------------------------
static __device__ __forceinline__ void t_chunk(const float* __restrict__ x,
                                               int n, int tb, SmemU* u, int tid) {
    const int s0  = tb * 128;
    const float* xin = x + (size_t)n * (C_ * HW_);
    const int lane = tid & 31;
    const int cb   = tid >> 5;

    #pragma unroll
    for (int h = 0; h < 2; h++) {
        float4 v[4];
        #pragma unroll
        for (int i = 0; i < 4; i++) {
            const int c = h * 32 + i * 8 + cb;
            v[i] = __ldcs((const float4*)(xin + (size_t)c * HW_ + s0) + lane);
        }
        #pragma unroll
        for (int i = 0; i < 4; i++) {
            const int c = h * 32 + i * 8 + cb;
            const unsigned int u0 = h2_as_u(__floats2half2_rn(v[i].x, v[i].y));
            const unsigned int u1 = h2_as_u(__floats2half2_rn(v[i].z, v[i].w));
            const int w0 = c * 64 + lane * 2;
            const int ws = w0 ^ (((c >> 3) & 7) << 2);
            *(uint2*)&u->smw[ws] = make_uint2(u0, u1);
        }
    }
    __syncthreads();

    uint4* ob = (uint4*)(g_xt + ((size_t)n * HW_ + s0) * C_);
    #pragma unroll
    for (int j = 0; j < 2; j++) {
        const int uu = tid + 256 * j;
        const int p2 = (uu >> 3) * 2;
        const int c8 = uu & 7;
        const int c0 = c8 * 8;
        const int sw = c8 << 2;

        unsigned int w8[8];
        #pragma unroll
        for (int jj = 0; jj < 8; jj++) {
            const int w = (c0 + jj) * 64 + (p2 >> 1);
            w8[jj] = u->smw[w ^ sw];
        }
        uint4 lo, hi;
        lo.x = __byte_perm(w8[0], w8[1], 0x5410);
        lo.y = __byte_perm(w8[2], w8[3], 0x5410);
        lo.z = __byte_perm(w8[4], w8[5], 0x5410);
        lo.w = __byte_perm(w8[6], w8[7], 0x5410);
        hi.x = __byte_perm(w8[0], w8[1], 0x7632);
        hi.y = __byte_perm(w8[2], w8[3], 0x7632);
        hi.z = __byte_perm(w8[4], w8[5], 0x7632);
        hi.w = __byte_perm(w8[6], w8[7], 0x7632);

        ob[p2 * 8 + c8]       = lo;
        ob[(p2 + 1) * 8 + c8] = hi;
    }
}

// -------------------------------------------------------------------------
// S body (R11, proven): 64 output pixels of one (n, ho) row.
// -------------------------------------------------------------------------
static __device__ __forceinline__ void s_chunk(const float* __restrict__ grid,
                                               float* __restrict__ out,
                                               int n, int sbi, SmemU* u, int tid) {
    const int wo_base = (sbi & 3) * 64;
    const int ho      = sbi >> 2;
    const int warp = tid >> 5;
    const int lane = tid & 31;

    // Phase A: warp-local coordinate setup (pixels warp*8 .. warp*8+7).
    if (lane < 8) {
        const int p = warp * 8 + lane;
        const float2* gp =
            (const float2*)(grid + (((size_t)n * HO_ + ho) * WO_ + wo_base) * 2);
        const float2 g = __ldcs(&gp[p]);

        const float ix = (g.x + 1.0f) * 0.5f * (float)(W_ - 1);
        const float iy = (g.y + 1.0f) * 0.5f * (float)(H_ - 1);

        const float x0f = floorf(ix);
        const float y0f = floorf(iy);
        const float wx1 = ix - x0f;
        const float wy1 = iy - y0f;
        const float wx0 = 1.0f - wx1;
        const float wy0 = 1.0f - wy1;

        const int xi = (int)x0f;
        const int yi = (int)y0f;
        const int x0 = min(max(xi,     0), W_ - 1);
        const int x1 = min(max(xi + 1, 0), W_ - 1);
        const int y0 = min(max(yi,     0), H_ - 1);
        const int y1 = min(max(yi + 1, 0), H_ - 1);

        int4 o;                                   // byte offsets (row = 128B)
        o.x = (y0 * W_ + x0) * (C_ * 2);
        o.y = (y0 * W_ + x1) * (C_ * 2);
        o.z = (y1 * W_ + x0) * (C_ * 2);
        o.w = (y1 * W_ + x1) * (C_ * 2);
        u->s.soff[p] = o;

        uint4 wq;
        wq.x = h2_as_u(__float2half2_rn(wy0 * wx0));
        wq.y = h2_as_u(__float2half2_rn(wy0 * wx1));
        wq.z = h2_as_u(__float2half2_rn(wy1 * wx0));
        wq.w = h2_as_u(__float2half2_rn(wy1 * wx1));
        u->s.swq[p] = wq;
    }
    __syncwarp();

    const char* xb = (const char*)(g_xt + (size_t)n * ((size_t)HW_ * C_));
    const int psel = lane >> 3;
    const int sub  = lane & 7;
    const int sb   = sub * 16;

    #pragma unroll
    for (int g = 0; g < 2; g++) {
        const int p = warp * 8 + g * 4 + psel;
        const int4  o  = u->s.soff[p];
        const uint4 wq = u->s.swq[p];

        const uint4 v00 = *(const uint4*)(xb + o.x + sb);
        const uint4 v01 = *(const uint4*)(xb + o.y + sb);
        const uint4 v10 = *(const uint4*)(xb + o.z + sb);
        const uint4 v11 = *(const uint4*)(xb + o.w + sb);

        const __half2 w00 = u_as_h2(wq.x);
        const __half2 w01 = u_as_h2(wq.y);
        const __half2 w10 = u_as_h2(wq.z);
        const __half2 w11 = u_as_h2(wq.w);

        unsigned int r[4];
        {
            __half2 a;
            a = __hmul2(u_as_h2(v00.x), w00);
            a = __hfma2(u_as_h2(v01.x), w01, a);
            a = __hfma2(u_as_h2(v10.x), w10, a);
            a = __hfma2(u_as_h2(v11.x), w11, a);
            r[0] = h2_as_u(a);
            a = __hmul2(u_as_h2(v00.y), w00);
            a = __hfma2(u_as_h2(v01.y), w01, a);
            a = __hfma2(u_as_h2(v10.y), w10, a);
            a = __hfma2(u_as_h2(v11.y), w11, a);
            r[1] = h2_as_u(a);
            a = __hmul2(u_as_h2(v00.z), w00);
            a = __hfma2(u_as_h2(v01.z), w01, a);
            a = __hfma2(u_as_h2(v10.z), w10, a);
            a = __hfma2(u_as_h2(v11.z), w11, a);
            r[2] = h2_as_u(a);
            a = __hmul2(u_as_h2(v00.w), w00);
            a = __hfma2(u_as_h2(v01.w), w01, a);
            a = __hfma2(u_as_h2(v10.w), w10, a);
            a = __hfma2(u_as_h2(v11.w), w11, a);
            r[3] = h2_as_u(a);
        }
        #pragma unroll
        for (int k = 0; k < 4; k++)
            u->s.smq[p * 33 + sub * 4 + k] = r[k];
    }
    __syncthreads();

    float* obase = out + (size_t)n * (C_ * HO_ * WO_) + (size_t)ho * WO_ + wo_base;
    #pragma unroll
    for (int it = 0; it < 4; it++) {
        const int uu = tid + 256 * it;
        const int c  = uu >> 4;
        const int q  = uu & 15;
        const int cp = c >> 1;
        const int hi = c & 1;

        float4 v;
        {
            const __half2 h0 = u_as_h2(u->s.smq[(q * 4 + 0) * 33 + cp]);
            const __half2 h1 = u_as_h2(u->s.smq[(q * 4 + 1) * 33 + cp]);
            const __half2 h2 = u_as_h2(u->s.smq[(q * 4 + 2) * 33 + cp]);
            const __half2 h3 = u_as_h2(u->s.smq[(q * 4 + 3) * 33 + cp]);
            v.x = hi ? __high2float(h0) : __low2float(h0);
            v.y = hi ? __high2float(h1) : __low2float(h1);
            v.z = hi ? __high2float(h2) : __low2float(h2);
            v.w = hi ? __high2float(h3) : __low2float(h3);
        }
        __stcs((float4*)(obase + (size_t)c * (HO_ * WO_) + q * 4), v);
    }
}

// -------------------------------------------------------------------------
// Pure transpose launch: images [n0, n0 + gridDim.y).
// -------------------------------------------------------------------------
__global__ __launch_bounds__(256, 4) void t_kernel(const float* __restrict__ x,
                                                   int n0) {
    __shared__ SmemU u;
    t_chunk(x, n0 + blockIdx.y, blockIdx.x, &u, threadIdx.x);
}

// -------------------------------------------------------------------------
// Mixed launch: 5120 blocks, bid%5<3 -> T (6 images, 3072 blocks),
// else -> S (2 images, 2048 blocks). S deps completed at the previous
// launch boundary — no intra-kernel sync.
// -------------------------------------------------------------------------
__global__ __launch_bounds__(256, 4) void mixed_kernel(
    const float* __restrict__ x, const float* __restrict__ grid,
    float* __restrict__ out, int nt0, int ns0) {
    __shared__ SmemU u;
    const int bid = blockIdx.x;
    const int tid = threadIdx.x;
    const int m   = bid % 5;
    const int d   = bid / 5;              // 0..1023

    if (m < 3) {                          // 3072 T blocks: 6 images
        const int tix = d * 3 + m;        // 0..3071
        t_chunk(x, nt0 + (tix >> 9), tix & 511, &u, tid);
    } else {                              // 2048 S blocks: 2 images
        const int six = d * 2 + (m - 3);  // 0..2047
        s_chunk(grid, out, ns0 + (six >> 10), six & 1023, &u, tid);
    }
}

// -------------------------------------------------------------------------
// Pure sample launch: images [n0, n0 + gridDim.y).
// -------------------------------------------------------------------------
__global__ __launch_bounds__(256, 5) void s_kernel(
    const float* __restrict__ grid, float* __restrict__ out, int n0) {
    __shared__ SmemU u;
    s_chunk(grid, out, n0 + blockIdx.y, blockIdx.x, &u, threadIdx.x);
}

extern "C" void kernel_launch(void* const* d_in, const int* in_sizes, int n_in,
                              void* d_out, int out_size) {
    const float* x    = (const float*)d_in[0];   // [N, C, H, W]
    const float* grid = (const float*)d_in[1];   // [N, HO, WO, 2]
    float* out        = (float*)d_out;           // [N, C, HO, WO]
    (void)in_sizes; (void)n_in; (void)out_size;

    // 3-launch pipeline, minimal pure-T exposure:
    // T(0,1) | T(2..7)+S(0,1) | S(2..7)
    t_kernel<<<dim3(512, 2), 256>>>(x, 0);
    mixed_kernel<<<5120, 256>>>(x, grid, out, 2, 0);
    s_kernel<<<dim3(1024, 6), 256>>>(grid, out, 2);
}